// round 9
// baseline (speedup 1.0000x reference)
#include <cuda_runtime.h>
#include <cuda_bf16.h>
#include <cstdint>

// MaxUnpooling2D scatter-add — R5 topology (best: 274.5us), with the zero-fill
// moved off the LSU onto the TMA/bulk-DMA engine.
//   step s (0..15): scatter phase h=s&1 of batch b=s>>1 into its 32MB output
//   half (predicated REDs, __ldcs stream)  ||  zero the 32MB half for step s+1
//   via cp.async.bulk shared->global (128 blocks, 256KB each, no per-lane STG).
// L2 set: 32MB scatter target + 32MB zero target + 32MB stream = 96MB < 126MB.
// The measured binder is per-message scatter rate on the SM LSU path; bulk
// stores bypass per-lane LSU issue, so REDs get the whole budget.

static constexpr int B         = 8;
static constexpr int IN_PER_B  = 1 << 22;        // elems per batch input
static constexpr int OUT_PER_B = 1 << 24;        // elems per batch output
static constexpr int HALF_OUT  = OUT_PER_B / 2;  // 2^23 elems, 32 MB

static constexpr int SCATTER_BLOCKS = (IN_PER_B / 4) / 256;  // 4096
static constexpr int ZERO_BLOCKS    = 128;                    // TMA zero blocks
static constexpr int ZBUF_BYTES     = 16384;                  // smem staging
static constexpr int ZERO_PER_BLOCK = (HALF_OUT * 4) / ZERO_BLOCKS; // 262144 B
static constexpr int COPIES_PER_BLOCK = ZERO_PER_BLOCK / ZBUF_BYTES; // 16

__device__ __forceinline__ uint32_t smem_u32(const void* p) {
    uint32_t a;
    asm("{ .reg .u64 t; cvta.to.shared.u64 t, %1; cvt.u32.u64 %0, t; }"
        : "=r"(a) : "l"(p));
    return a;
}

// Blocks [0, SCATTER_BLOCKS): predicated scatter (R5-identical).
// Blocks [SCATTER_BLOCKS, +ZERO_BLOCKS): TMA bulk-zero 256KB each.
__global__ void __launch_bounds__(256)
pipe_half_kernel(const float4* __restrict__ vals4,
                 const int4*  __restrict__ idx4,
                 float* __restrict__ out_scatter,  // batch output base
                 int phase,                        // 0: idx<2^23, 1: >=
                 char* __restrict__ out_zero)      // 32MB region or nullptr
{
    __shared__ __align__(128) char zbuf[ZBUF_BYTES];
    int bid = blockIdx.x;
    if (bid < SCATTER_BLOCKS) {
        int i = bid * 256 + threadIdx.x;
        float4 v = __ldcs(vals4 + i);
        int4   x = __ldcs(idx4 + i);
        if ((x.x >> 23) == phase) atomicAdd(out_scatter + x.x, v.x);
        if ((x.y >> 23) == phase) atomicAdd(out_scatter + x.y, v.y);
        if ((x.z >> 23) == phase) atomicAdd(out_scatter + x.z, v.z);
        if ((x.w >> 23) == phase) atomicAdd(out_scatter + x.w, v.w);
    } else {
        // Zero the smem staging buffer (once), then DMA it out 16x.
        float4* z4 = (float4*)zbuf;
        float4 z = make_float4(0.f, 0.f, 0.f, 0.f);
        for (int i = threadIdx.x; i < ZBUF_BYTES / 16; i += 256) z4[i] = z;
        __syncthreads();
        if (threadIdx.x == 0) {
            asm volatile("fence.proxy.async.shared::cta;" ::: "memory");
            uint32_t src = smem_u32(zbuf);
            char* dst = out_zero + (size_t)(bid - SCATTER_BLOCKS) * ZERO_PER_BLOCK;
            #pragma unroll
            for (int c = 0; c < COPIES_PER_BLOCK; c++) {
                asm volatile(
                    "cp.async.bulk.global.shared::cta.bulk_group [%0], [%1], %2;"
                    :: "l"(dst + (size_t)c * ZBUF_BYTES), "r"(src),
                       "n"(ZBUF_BYTES) : "memory");
            }
            asm volatile("cp.async.bulk.commit_group;" ::: "memory");
            asm volatile("cp.async.bulk.wait_group 0;" ::: "memory");
        }
    }
}

extern "C" void kernel_launch(void* const* d_in, const int* in_sizes, int n_in,
                              void* d_out, int out_size)
{
    const float* vals = (const float*)d_in[0];
    const int*   idx  = (const int*)d_in[1];
    float* out = (float*)d_out;

    // Prologue: zero batch 0, half 0 (32MB) via memset node.
    cudaMemsetAsync(d_out, 0, (size_t)HALF_OUT * sizeof(float));

    // 16 half-steps: step s scatters (b=s>>1, phase=s&1), zeroes region s+1.
    for (int s = 0; s < 2 * B; s++) {
        int b = s >> 1;
        int h = s & 1;
        const float4* v4 = (const float4*)(vals + (size_t)b * IN_PER_B);
        const int4*   x4 = (const int4*)(idx + (size_t)b * IN_PER_B);
        float* out_b = out + (size_t)b * OUT_PER_B;

        if (s + 1 < 2 * B) {
            char* zdst = (char*)(out + (size_t)(s + 1) * HALF_OUT);
            pipe_half_kernel<<<SCATTER_BLOCKS + ZERO_BLOCKS, 256>>>(
                v4, x4, out_b, h, zdst);
        } else {
            pipe_half_kernel<<<SCATTER_BLOCKS, 256>>>(v4, x4, out_b, h, nullptr);
        }
    }
}

// round 12
// speedup vs baseline: 2.0223x; 2.0223x over previous
#include <cuda_runtime.h>
#include <cuda_bf16.h>
#include <cstdint>

// MaxUnpooling2D scatter-add — R5 champion topology (274.5us), consolidated.
//   step s (0..15): scatter phase h=s&1 of batch b=s>>1 into its 32MB output
//   half (predicated REDs, __ldcs streaming loads)  ||  zero the 32MB half
//   needed at step s+1 (2048 blocks x 4 coalesced STG.128 per thread).
// L2 set per step: 32MB scatter target + 32MB zero target + 32MB stream
// = 96MB < 126MB L2 -> atomics stay L2 hits, output reaches DRAM once.
// Floor: 33.5M atomic messages at the LTS atomic-ALU ceiling (~184G/s @NAT);
// measured ~150G/s. Zero-fill is arranged to hide under it.

static constexpr int B         = 8;
static constexpr int IN_PER_B  = 1 << 22;        // elems per batch input
static constexpr int OUT_PER_B = 1 << 24;        // elems per batch output
static constexpr int HALF_OUT  = OUT_PER_B / 2;  // 2^23 elems, 32 MB

static constexpr int SCATTER_BLOCKS = (IN_PER_B / 4) / 256;      // 4096
// zero: 2048 blocks x 256 threads x 4 float4 = 2^23 floats
static constexpr int ZERO_BLOCKS    = HALF_OUT / (256 * 16);     // 2048

// Blocks [0, SCATTER_BLOCKS): scatter phase `phase` of this batch.
// Blocks [SCATTER_BLOCKS, +ZERO_BLOCKS): zero the next 32MB half-region.
__global__ void __launch_bounds__(256)
pipe_half_kernel(const float4* __restrict__ vals4,
                 const int4*  __restrict__ idx4,
                 float* __restrict__ out_scatter,  // batch output base
                 int phase,                        // 0: idx<2^23, 1: idx>=2^23
                 float4* __restrict__ out_zero)    // 32MB region or nullptr
{
    int bid = blockIdx.x;
    if (bid < SCATTER_BLOCKS) {
        int i = bid * 256 + threadIdx.x;
        float4 v = __ldcs(vals4 + i);
        int4   x = __ldcs(idx4 + i);
        if ((x.x >> 23) == phase) atomicAdd(out_scatter + x.x, v.x);
        if ((x.y >> 23) == phase) atomicAdd(out_scatter + x.y, v.y);
        if ((x.z >> 23) == phase) atomicAdd(out_scatter + x.z, v.z);
        if ((x.w >> 23) == phase) atomicAdd(out_scatter + x.w, v.w);
    } else {
        // 4 coalesced float4 stores per thread, warp-contiguous.
        int base = (bid - SCATTER_BLOCKS) * (256 * 4) + threadIdx.x;
        float4 z = make_float4(0.f, 0.f, 0.f, 0.f);
        out_zero[base]           = z;
        out_zero[base + 256]     = z;
        out_zero[base + 512]     = z;
        out_zero[base + 768]     = z;
    }
}

extern "C" void kernel_launch(void* const* d_in, const int* in_sizes, int n_in,
                              void* d_out, int out_size)
{
    const float* vals = (const float*)d_in[0];
    const int*   idx  = (const int*)d_in[1];
    float* out = (float*)d_out;

    // Prologue: zero batch 0, half 0 (32MB) via memset node (off the SMs'
    // critical path as much as possible; one node instead of a zero kernel).
    cudaMemsetAsync(d_out, 0, (size_t)HALF_OUT * sizeof(float));

    // 16 half-steps: step s scatters (b=s>>1, phase=s&1), zeroes region s+1.
    for (int s = 0; s < 2 * B; s++) {
        int b = s >> 1;
        int h = s & 1;
        const float4* v4 = (const float4*)(vals + (size_t)b * IN_PER_B);
        const int4*   x4 = (const int4*)(idx + (size_t)b * IN_PER_B);
        float* out_b = out + (size_t)b * OUT_PER_B;

        if (s + 1 < 2 * B) {
            float4* zdst = (float4*)(out + (size_t)(s + 1) * HALF_OUT);
            pipe_half_kernel<<<SCATTER_BLOCKS + ZERO_BLOCKS, 256>>>(
                v4, x4, out_b, h, zdst);
        } else {
            pipe_half_kernel<<<SCATTER_BLOCKS, 256>>>(v4, x4, out_b, h, nullptr);
        }
    }
}